// round 1
// baseline (speedup 1.0000x reference)
#include <cuda_runtime.h>
#include <math.h>

// Problem constants
#define Bsz  32
#define Tlen 1024
#define Dd   512
#define Hh   512
#define NG   1536   // 3*H, columns of w_ih actually used
#define C4H  2048   // 4*H

// -------- device scratch (static: allocation at module load, allowed) --------
__device__ float g_wih[Dd * NG];                       // sampled w_ih[:, :3H], [d][c]
__device__ float g_wt[NG * Dd];                        // scan weights, transposed [c'][k]
                                                       // c' <1024 -> w_hh col c' (r,z), c'>=1024 -> w_hh col c'+512 (n)
__device__ float g_bias[C4H];                          // sampled bias
__device__ float g_xg[(size_t)Bsz * Tlen * NG];        // xg[(b*T+t)][c], 201 MB
__device__ float g_h[2][Bsz * Hh];                     // ping-pong hidden state
__device__ unsigned g_bar[Tlen];                       // grid barrier counters

__device__ __forceinline__ float softplusf_(float x) {
    return x > 20.f ? x : log1pf(__expf(x));
}
__device__ __forceinline__ float sigmoidf_(float x) {
    return 1.f / (1.f + __expf(-x));
}

// ---------------- prologue: sample weights + reset barriers ----------------
__global__ void sample_all_kernel(const float* __restrict__ wih_mu, const float* __restrict__ wih_rho,
                                  const float* __restrict__ eps_ih,
                                  const float* __restrict__ whh_mu, const float* __restrict__ whh_rho,
                                  const float* __restrict__ eps_hh,
                                  const float* __restrict__ b_mu, const float* __restrict__ b_rho,
                                  const float* __restrict__ eps_b) {
    int i = blockIdx.x * blockDim.x + threadIdx.x;
    const int N1 = Dd * NG;          // 786432
    const int N2 = N1 + NG * Dd;     // + 786432
    const int N3 = N2 + C4H;
    const int N4 = N3 + Tlen;
    if (i < N1) {
        int d = i / NG, c = i % NG;
        int s = d * C4H + c;
        g_wih[i] = wih_mu[s] + softplusf_(wih_rho[s]) * eps_ih[s];
    } else if (i < N2) {
        int j = i - N1;
        int cp = j / Dd, k = j % Dd;
        int col = (cp < 1024) ? cp : cp + 512;   // n-gate cols are w_hh[:, 3H:4H]
        int s = k * C4H + col;
        g_wt[j] = whh_mu[s] + softplusf_(whh_rho[s]) * eps_hh[s];
    } else if (i < N3) {
        int j = i - N2;
        g_bias[j] = b_mu[j] + softplusf_(b_rho[j]) * eps_b[j];
    } else if (i < N4) {
        g_bar[i - N3] = 0u;
    }
}

// ---------------- xg GEMM: C[m][c] = sum_k x[m][k] * g_wih[k][c] ----------------
// M = 32768 (m = b*T + t), N = 1536, K = 512.
#define GM 32768
#define GN 1536
#define GK 512

__global__ __launch_bounds__(256) void xg_gemm_kernel(const float* __restrict__ A) {
    __shared__ float As[8][128];   // transposed A tile
    __shared__ float Bs[8][128];

    const int tid = threadIdx.x;
    const int bx = blockIdx.x;   // 12 col tiles
    const int by = blockIdx.y;   // 256 row tiles

    const float* Ab = A + (size_t)by * 128 * GK;
    const float* Bb = g_wih + bx * 128;
    float* Cb = g_xg + (size_t)by * 128 * GN + bx * 128;

    const int aRow = tid >> 1;
    const int aCol = (tid & 1) * 4;
    const int bRow = tid >> 5;
    const int bCol = (tid & 31) * 4;
    const int tx = tid & 15;
    const int ty = tid >> 4;

    float acc[8][8];
#pragma unroll
    for (int i = 0; i < 8; i++)
#pragma unroll
        for (int j = 0; j < 8; j++) acc[i][j] = 0.f;

    for (int k0 = 0; k0 < GK; k0 += 8) {
        float4 a4 = *(const float4*)&Ab[(size_t)aRow * GK + k0 + aCol];
        float4 b4 = *(const float4*)&Bb[(size_t)(k0 + bRow) * GN + bCol];
        __syncthreads();
        As[aCol + 0][aRow] = a4.x;
        As[aCol + 1][aRow] = a4.y;
        As[aCol + 2][aRow] = a4.z;
        As[aCol + 3][aRow] = a4.w;
        *(float4*)&Bs[bRow][bCol] = b4;
        __syncthreads();
#pragma unroll
        for (int kk = 0; kk < 8; kk++) {
            float ar[8], br[8];
            *(float4*)&ar[0] = *(const float4*)&As[kk][ty * 4];
            *(float4*)&ar[4] = *(const float4*)&As[kk][64 + ty * 4];
            *(float4*)&br[0] = *(const float4*)&Bs[kk][tx * 4];
            *(float4*)&br[4] = *(const float4*)&Bs[kk][64 + tx * 4];
#pragma unroll
            for (int i = 0; i < 8; i++)
#pragma unroll
                for (int j = 0; j < 8; j++) acc[i][j] += ar[i] * br[j];
        }
    }
#pragma unroll
    for (int i = 0; i < 8; i++) {
        int row = (i < 4) ? (ty * 4 + i) : (64 + ty * 4 + (i - 4));
        float4 v0 = make_float4(acc[i][0], acc[i][1], acc[i][2], acc[i][3]);
        float4 v1 = make_float4(acc[i][4], acc[i][5], acc[i][6], acc[i][7]);
        *(float4*)&Cb[(size_t)row * GN + tx * 4] = v0;
        *(float4*)&Cb[(size_t)row * GN + 64 + tx * 4] = v1;
    }
}

// ---------------- persistent GRU scan ----------------
// 128 CTAs, each owns 4 hidden columns (j0..j0+3) for all 3 gates.
// W columns live in shared for the whole kernel. h broadcast via L2 each step.
#define SCAN_CTAS 128

struct ScanSmem {
    float h[32][516];        // padded: 516 % 32 == 4 -> conflict-free LDS.128 across b
    float w[3][4][512];      // [gate][jj][k]
    float xg[3][32][4];      // [gate][b][jj]
    float red[128][3];       // k-half reduction
};

__global__ __launch_bounds__(256, 1) void scan_kernel(const float* __restrict__ h0,
                                                      float* __restrict__ out,
                                                      int write_last) {
    extern __shared__ float smem_raw[];
    ScanSmem* S = (ScanSmem*)smem_raw;

    const int tid = threadIdx.x;
    const int j0 = blockIdx.x * 4;
    const int b  = tid & 31;
    const int jj = (tid >> 5) & 3;
    const int kh = tid >> 7;          // 0 or 1: which 256-wide k half
    const int jg = j0 + jj;

    // load this CTA's 12 weight columns into shared (once)
    for (int i = tid; i < 12 * 512; i += 256) {
        int g = i / 2048;
        int rem = i % 2048;
        int jjj = rem / 512;
        int k = rem % 512;
        int cp = (g == 0) ? (j0 + jjj) : (g == 1) ? (512 + j0 + jjj) : (1024 + j0 + jjj);
        S->w[g][jjj][k] = g_wt[cp * 512 + k];
    }
    float brz_r = 0.f, brz_z = 0.f, bn = 0.f, bhn = 0.f;
    if (tid < 128) {
        brz_r = g_bias[jg];
        brz_z = g_bias[512 + jg];
        bn    = g_bias[1024 + jg];
        bhn   = g_bias[1536 + jg];
    }
    __syncthreads();

    for (int t = 0; t < Tlen; t++) {
        // ---- load h into shared (L1-bypassing: written by other SMs) ----
        const float* hsrc = (t == 0) ? h0 : g_h[t & 1];
        for (int i = tid * 4; i < 16384; i += 1024) {
            float4 v;
            if (t == 0) v = *(const float4*)&hsrc[i];
            else        v = __ldcg((const float4*)&hsrc[i]);
            int bb = i >> 9;
            int k = i & 511;
            *(float4*)&S->h[bb][k] = v;
        }
        // ---- xg for this step ----
        if (tid < 96) {
            int g = tid >> 5;
            int bb = tid & 31;
            int c0 = g * 512 + j0;
            *(float4*)&S->xg[g][bb][0] =
                *(const float4*)&g_xg[((size_t)bb * Tlen + t) * NG + c0];
        }
        __syncthreads();

        // ---- partial dots over this thread's k half ----
        float ar = 0.f, az = 0.f, an = 0.f;
        const float* hp = &S->h[b][kh * 256];
        const float* wr = &S->w[0][jj][kh * 256];
        const float* wz = &S->w[1][jj][kh * 256];
        const float* wn = &S->w[2][jj][kh * 256];
#pragma unroll 8
        for (int k = 0; k < 256; k += 4) {
            float4 h4 = *(const float4*)&hp[k];
            float4 w4;
            w4 = *(const float4*)&wr[k];
            ar += h4.x * w4.x + h4.y * w4.y + h4.z * w4.z + h4.w * w4.w;
            w4 = *(const float4*)&wz[k];
            az += h4.x * w4.x + h4.y * w4.y + h4.z * w4.z + h4.w * w4.w;
            w4 = *(const float4*)&wn[k];
            an += h4.x * w4.x + h4.y * w4.y + h4.z * w4.z + h4.w * w4.w;
        }
        if (kh) {
            S->red[tid - 128][0] = ar;
            S->red[tid - 128][1] = az;
            S->red[tid - 128][2] = an;
        }
        __syncthreads();

        if (tid < 128) {
            ar += S->red[tid][0];
            az += S->red[tid][1];
            an += S->red[tid][2];
            float r = sigmoidf_(ar + S->xg[0][b][jj] + brz_r);
            float z = sigmoidf_(az + S->xg[1][b][jj] + brz_z);
            float n = tanhf(S->xg[2][b][jj] + bn + r * (an + bhn));
            float hprev = S->h[b][jg];
            float hnew = (1.f - z) * n + z * hprev;
            g_h[(t + 1) & 1][b * Hh + jg] = hnew;
            out[((size_t)b * Tlen + t) * Hh + jg] = hnew;
            if (write_last && t == Tlen - 1)
                out[(size_t)Bsz * Tlen * Hh + b * Hh + jg] = hnew;
        }

        // ---- grid barrier ----
        if (t < Tlen - 1) {
            __threadfence();
            __syncthreads();
            if (tid == 0) {
                atomicAdd(&g_bar[t], 1u);
                while (*(volatile unsigned*)&g_bar[t] < (unsigned)SCAN_CTAS) { }
            }
            __syncthreads();
        }
    }
}

// ---------------- launch ----------------
extern "C" void kernel_launch(void* const* d_in, const int* in_sizes, int n_in,
                              void* d_out, int out_size) {
    const float* x       = (const float*)d_in[0];
    const float* h0      = (const float*)d_in[1];
    const float* wih_mu  = (const float*)d_in[2];
    const float* wih_rho = (const float*)d_in[3];
    const float* whh_mu  = (const float*)d_in[4];
    const float* whh_rho = (const float*)d_in[5];
    const float* b_mu    = (const float*)d_in[6];
    const float* b_rho   = (const float*)d_in[7];
    const float* eps_ih  = (const float*)d_in[8];
    const float* eps_hh  = (const float*)d_in[9];
    const float* eps_b   = (const float*)d_in[10];
    float* out = (float*)d_out;

    // 1) sample weights into scratch + reset barrier counters
    {
        int total = Dd * NG + NG * Dd + C4H + Tlen;
        int blocks = (total + 255) / 256;
        sample_all_kernel<<<blocks, 256>>>(wih_mu, wih_rho, eps_ih,
                                           whh_mu, whh_rho, eps_hh,
                                           b_mu, b_rho, eps_b);
    }
    // 2) xg = x @ w_ih[:, :3H]
    {
        dim3 grid(GN / 128, GM / 128);
        xg_gemm_kernel<<<grid, 256>>>(x);
    }
    // 3) persistent scan
    {
        int smem = (int)sizeof(ScanSmem);
        cudaFuncSetAttribute(scan_kernel, cudaFuncAttributeMaxDynamicSharedMemorySize, smem);
        int write_last = (out_size >= Bsz * Tlen * Hh + Bsz * Hh) ? 1 : 0;
        scan_kernel<<<SCAN_CTAS, 256, smem>>>(h0, out, write_last);
    }
}

// round 2
// speedup vs baseline: 1.0038x; 1.0038x over previous
#include <cuda_runtime.h>
#include <math.h>

// Problem constants
#define Bsz  32
#define Tlen 1024
#define Dd   512
#define Hh   512
#define NG   1536   // 3*H, columns of w_ih actually used
#define C4H  2048   // 4*H

// -------- device scratch --------
__device__ float g_wih[Dd * NG];                       // sampled w_ih[:, :3H], [d][c]
__device__ float g_wt[NG * Dd];                        // scan weights, transposed [c'][k]
__device__ float g_bias[C4H];                          // sampled bias
__device__ float g_xg[(size_t)Bsz * Tlen * NG];        // xg[(b*T+t)][c]
__device__ float g_h[2][Bsz * Hh];                     // ping-pong hidden state
__device__ unsigned g_bar[Tlen];                       // grid barrier counters

__device__ __forceinline__ float softplusf_(float x) {
    return x > 20.f ? x : log1pf(__expf(x));
}
__device__ __forceinline__ float sigmoidf_(float x) {
    return 1.f / (1.f + __expf(-x));
}

// ---------------- prologue: sample weights + reset barriers ----------------
__global__ void sample_all_kernel(const float* __restrict__ wih_mu, const float* __restrict__ wih_rho,
                                  const float* __restrict__ eps_ih,
                                  const float* __restrict__ whh_mu, const float* __restrict__ whh_rho,
                                  const float* __restrict__ eps_hh,
                                  const float* __restrict__ b_mu, const float* __restrict__ b_rho,
                                  const float* __restrict__ eps_b) {
    int i = blockIdx.x * blockDim.x + threadIdx.x;
    const int N1 = Dd * NG;
    const int N2 = N1 + NG * Dd;
    const int N3 = N2 + C4H;
    const int N4 = N3 + Tlen;
    if (i < N1) {
        int d = i / NG, c = i % NG;
        int s = d * C4H + c;
        g_wih[i] = wih_mu[s] + softplusf_(wih_rho[s]) * eps_ih[s];
    } else if (i < N2) {
        int j = i - N1;
        int cp = j / Dd, k = j % Dd;
        int col = (cp < 1024) ? cp : cp + 512;
        int s = k * C4H + col;
        g_wt[j] = whh_mu[s] + softplusf_(whh_rho[s]) * eps_hh[s];
    } else if (i < N3) {
        int j = i - N2;
        g_bias[j] = b_mu[j] + softplusf_(b_rho[j]) * eps_b[j];
    } else if (i < N4) {
        g_bar[i - N3] = 0u;
    }
}

// ---------------- xg GEMM: C[m][c] = sum_k x[m][k] * g_wih[k][c] ----------------
// M = 32768, N = 1536, K = 512. 128x128 tile, BK=16, double-buffered smem.
#define GM 32768
#define GN 1536
#define GK 512
#define BKk 16

__global__ __launch_bounds__(256, 2) void xg_gemm_kernel(const float* __restrict__ A) {
    __shared__ float As[2][BKk][128];   // transposed A tile: As[kk][row]
    __shared__ float Bs[2][BKk][128];

    const int tid = threadIdx.x;
    const int bx = blockIdx.x;   // 12 col tiles
    const int by = blockIdx.y;   // 256 row tiles

    const float* Ab = A + (size_t)by * 128 * GK;
    const float* Bb = g_wih + bx * 128;
    float* Cb = g_xg + (size_t)by * 128 * GN + bx * 128;

    // A load mapping: 2 threads per row, each 8 cols (2 float4)
    const int aRow  = tid >> 1;
    const int aColH = (tid & 1) * 8;
    // B load mapping: 16 threads per k-row, each 8 cols (2 float4)
    const int bKr = tid >> 4;
    const int bC  = (tid & 15) * 8;

    const int tx = tid & 15;
    const int ty = tid >> 4;

    float acc[8][8];
#pragma unroll
    for (int i = 0; i < 8; i++)
#pragma unroll
        for (int j = 0; j < 8; j++) acc[i][j] = 0.f;

    float4 a0, a1, b0, b1;

    // prologue: load tile 0
    a0 = *(const float4*)&Ab[(size_t)aRow * GK + aColH];
    a1 = *(const float4*)&Ab[(size_t)aRow * GK + aColH + 4];
    b0 = *(const float4*)&Bb[(size_t)bKr * GN + bC];
    b1 = *(const float4*)&Bb[(size_t)bKr * GN + bC + 4];
    {
        float av[8] = {a0.x, a0.y, a0.z, a0.w, a1.x, a1.y, a1.z, a1.w};
#pragma unroll
        for (int i = 0; i < 8; i++) As[0][aColH + i][aRow] = av[i];
        *(float4*)&Bs[0][bKr][bC] = b0;
        *(float4*)&Bs[0][bKr][bC + 4] = b1;
    }
    __syncthreads();

    for (int k0 = 0; k0 < GK; k0 += BKk) {
        const int buf = (k0 / BKk) & 1;
        const bool more = (k0 + BKk) < GK;
        if (more) {
            a0 = *(const float4*)&Ab[(size_t)aRow * GK + k0 + BKk + aColH];
            a1 = *(const float4*)&Ab[(size_t)aRow * GK + k0 + BKk + aColH + 4];
            b0 = *(const float4*)&Bb[(size_t)(k0 + BKk + bKr) * GN + bC];
            b1 = *(const float4*)&Bb[(size_t)(k0 + BKk + bKr) * GN + bC + 4];
        }
#pragma unroll
        for (int kk = 0; kk < BKk; kk++) {
            float ar[8], br[8];
            *(float4*)&ar[0] = *(const float4*)&As[buf][kk][ty * 4];
            *(float4*)&ar[4] = *(const float4*)&As[buf][kk][64 + ty * 4];
            *(float4*)&br[0] = *(const float4*)&Bs[buf][kk][tx * 4];
            *(float4*)&br[4] = *(const float4*)&Bs[buf][kk][64 + tx * 4];
#pragma unroll
            for (int i = 0; i < 8; i++)
#pragma unroll
                for (int j = 0; j < 8; j++) acc[i][j] += ar[i] * br[j];
        }
        if (more) {
            const int nbuf = buf ^ 1;
            float av[8] = {a0.x, a0.y, a0.z, a0.w, a1.x, a1.y, a1.z, a1.w};
#pragma unroll
            for (int i = 0; i < 8; i++) As[nbuf][aColH + i][aRow] = av[i];
            *(float4*)&Bs[nbuf][bKr][bC] = b0;
            *(float4*)&Bs[nbuf][bKr][bC + 4] = b1;
            __syncthreads();
        }
    }
#pragma unroll
    for (int i = 0; i < 8; i++) {
        int row = (i < 4) ? (ty * 4 + i) : (64 + ty * 4 + (i - 4));
        float4 v0 = make_float4(acc[i][0], acc[i][1], acc[i][2], acc[i][3]);
        float4 v1 = make_float4(acc[i][4], acc[i][5], acc[i][6], acc[i][7]);
        *(float4*)&Cb[(size_t)row * GN + tx * 4] = v0;
        *(float4*)&Cb[(size_t)row * GN + 64 + tx * 4] = v1;
    }
}

// ---------------- persistent GRU scan ----------------
#define SCAN_CTAS 128

struct ScanSmem {
    float h[32][516];        // padded: conflict-free LDS.128 across b
    float w[3][4][512];      // [gate][jj][k]
    float xg[3][32][4];      // [gate][b][jj]
    float red[128][3];       // k-half reduction
};

__global__ __launch_bounds__(256, 1) void scan_kernel(const float* __restrict__ h0,
                                                      float* __restrict__ out,
                                                      int write_last) {
    extern __shared__ float smem_raw[];
    ScanSmem* S = (ScanSmem*)smem_raw;

    const int tid = threadIdx.x;
    const int j0 = blockIdx.x * 4;
    const int b  = tid & 31;
    const int jj = (tid >> 5) & 3;
    const int kh = tid >> 7;
    const int jg = j0 + jj;

    for (int i = tid; i < 12 * 512; i += 256) {
        int g = i / 2048;
        int rem = i % 2048;
        int jjj = rem / 512;
        int k = rem % 512;
        int cp = (g == 0) ? (j0 + jjj) : (g == 1) ? (512 + j0 + jjj) : (1024 + j0 + jjj);
        S->w[g][jjj][k] = g_wt[cp * 512 + k];
    }
    float brz_r = 0.f, brz_z = 0.f, bn = 0.f, bhn = 0.f;
    if (tid < 128) {
        brz_r = g_bias[jg];
        brz_z = g_bias[512 + jg];
        bn    = g_bias[1024 + jg];
        bhn   = g_bias[1536 + jg];
    }
    __syncthreads();

    for (int t = 0; t < Tlen; t++) {
        const float* hsrc = (t == 0) ? h0 : g_h[t & 1];
        for (int i = tid * 4; i < 16384; i += 1024) {
            float4 v;
            if (t == 0) v = *(const float4*)&hsrc[i];
            else        v = __ldcg((const float4*)&hsrc[i]);
            int bb = i >> 9;
            int k = i & 511;
            *(float4*)&S->h[bb][k] = v;
        }
        if (tid < 96) {
            int g = tid >> 5;
            int bb = tid & 31;
            int c0 = g * 512 + j0;
            *(float4*)&S->xg[g][bb][0] =
                *(const float4*)&g_xg[((size_t)bb * Tlen + t) * NG + c0];
        }
        __syncthreads();

        float ar = 0.f, az = 0.f, an = 0.f;
        const float* hp = &S->h[b][kh * 256];
        const float* wr = &S->w[0][jj][kh * 256];
        const float* wz = &S->w[1][jj][kh * 256];
        const float* wn = &S->w[2][jj][kh * 256];
#pragma unroll 8
        for (int k = 0; k < 256; k += 4) {
            float4 h4 = *(const float4*)&hp[k];
            float4 w4;
            w4 = *(const float4*)&wr[k];
            ar += h4.x * w4.x + h4.y * w4.y + h4.z * w4.z + h4.w * w4.w;
            w4 = *(const float4*)&wz[k];
            az += h4.x * w4.x + h4.y * w4.y + h4.z * w4.z + h4.w * w4.w;
            w4 = *(const float4*)&wn[k];
            an += h4.x * w4.x + h4.y * w4.y + h4.z * w4.z + h4.w * w4.w;
        }
        if (kh) {
            S->red[tid - 128][0] = ar;
            S->red[tid - 128][1] = az;
            S->red[tid - 128][2] = an;
        }
        __syncthreads();

        if (tid < 128) {
            ar += S->red[tid][0];
            az += S->red[tid][1];
            an += S->red[tid][2];
            float r = sigmoidf_(ar + S->xg[0][b][jj] + brz_r);
            float z = sigmoidf_(az + S->xg[1][b][jj] + brz_z);
            float n = tanhf(S->xg[2][b][jj] + bn + r * (an + bhn));
            float hprev = S->h[b][jg];
            float hnew = (1.f - z) * n + z * hprev;
            g_h[(t + 1) & 1][b * Hh + jg] = hnew;
            out[((size_t)b * Tlen + t) * Hh + jg] = hnew;
            if (write_last && t == Tlen - 1)
                out[(size_t)Bsz * Tlen * Hh + b * Hh + jg] = hnew;
        }

        // ---- grid barrier: release-arrive + acquire-poll (no full fence) ----
        if (t < Tlen - 1) {
            __syncthreads();
            if (tid == 0) {
                unsigned* bp = &g_bar[t];
                asm volatile("red.release.gpu.global.add.u32 [%0], %1;"
                             :: "l"(bp), "r"(1u) : "memory");
                unsigned v;
                do {
                    asm volatile("ld.acquire.gpu.global.u32 %0, [%1];"
                                 : "=r"(v) : "l"(bp) : "memory");
                } while (v < (unsigned)SCAN_CTAS);
            }
            __syncthreads();
        }
    }
}

// ---------------- launch ----------------
extern "C" void kernel_launch(void* const* d_in, const int* in_sizes, int n_in,
                              void* d_out, int out_size) {
    const float* x       = (const float*)d_in[0];
    const float* h0      = (const float*)d_in[1];
    const float* wih_mu  = (const float*)d_in[2];
    const float* wih_rho = (const float*)d_in[3];
    const float* whh_mu  = (const float*)d_in[4];
    const float* whh_rho = (const float*)d_in[5];
    const float* b_mu    = (const float*)d_in[6];
    const float* b_rho   = (const float*)d_in[7];
    const float* eps_ih  = (const float*)d_in[8];
    const float* eps_hh  = (const float*)d_in[9];
    const float* eps_b   = (const float*)d_in[10];
    float* out = (float*)d_out;

    {
        int total = Dd * NG + NG * Dd + C4H + Tlen;
        int blocks = (total + 255) / 256;
        sample_all_kernel<<<blocks, 256>>>(wih_mu, wih_rho, eps_ih,
                                           whh_mu, whh_rho, eps_hh,
                                           b_mu, b_rho, eps_b);
    }
    {
        dim3 grid(GN / 128, GM / 128);
        xg_gemm_kernel<<<grid, 256>>>(x);
    }
    {
        int smem = (int)sizeof(ScanSmem);
        cudaFuncSetAttribute(scan_kernel, cudaFuncAttributeMaxDynamicSharedMemorySize, smem);
        int write_last = (out_size >= Bsz * Tlen * Hh + Bsz * Hh) ? 1 : 0;
        scan_kernel<<<SCAN_CTAS, 256, smem>>>(h0, out, write_last);
    }
}

// round 3
// speedup vs baseline: 1.4492x; 1.4437x over previous
#include <cuda_runtime.h>
#include <math.h>

// Problem constants
#define Bsz  32
#define Tlen 1024
#define Dd   512
#define Hh   512
#define NG   1536   // 3*H
#define C4H  2048   // 4*H

// -------- device scratch --------
__device__ float g_wih[Dd * NG];                 // sampled w_ih[:, :3H], [d][c] (GEMM B)
__device__ float g_wt2[32 * 512 * 48];           // scan weights [jg][k][c], c = g*16+jl
__device__ float g_bias[C4H];
__device__ float g_xg[(size_t)Bsz * Tlen * NG];  // [t][bg][jg][b8][48]
__device__ float g_h[2][Bsz * Hh];               // ping-pong hidden [b][k]
__device__ unsigned g_bar[4 * Tlen];             // per-batch-group barrier counters

__device__ __forceinline__ float softplusf_(float x) {
    return x > 20.f ? x : log1pf(__expf(x));
}

// f32x2 helpers
__device__ __forceinline__ unsigned long long pack2(float x) {
    unsigned long long d; unsigned u = __float_as_uint(x);
    asm("mov.b64 %0, {%1, %1};" : "=l"(d) : "r"(u));
    return d;
}
__device__ __forceinline__ void fma2(unsigned long long& d, unsigned long long a, unsigned long long b) {
    asm("fma.rn.f32x2 %0, %1, %2, %0;" : "+l"(d) : "l"(a), "l"(b));
}
__device__ __forceinline__ unsigned long long add2(unsigned long long a, unsigned long long b) {
    unsigned long long d;
    asm("add.rn.f32x2 %0, %1, %2;" : "=l"(d) : "l"(a), "l"(b));
    return d;
}

// ---------------- prologue: sample weights + reset barriers ----------------
__global__ void sample_all_kernel(const float* __restrict__ wih_mu, const float* __restrict__ wih_rho,
                                  const float* __restrict__ eps_ih,
                                  const float* __restrict__ whh_mu, const float* __restrict__ whh_rho,
                                  const float* __restrict__ eps_hh,
                                  const float* __restrict__ b_mu, const float* __restrict__ b_rho,
                                  const float* __restrict__ eps_b) {
    int i = blockIdx.x * blockDim.x + threadIdx.x;
    const int N1 = Dd * NG;            // w_ih
    const int N2 = N1 + 32 * 512 * 48; // w_hh scan layout
    const int N3 = N2 + C4H;
    const int N4 = N3 + 4 * Tlen;
    if (i < N1) {
        int d = i / NG, c = i % NG;
        int s = d * C4H + c;
        g_wih[i] = wih_mu[s] + softplusf_(wih_rho[s]) * eps_ih[s];
    } else if (i < N2) {
        int jj = i - N1;
        int jg = jj / 24576;           // 512*48
        int r = jj % 24576;
        int k = r / 48;
        int c = r % 48;
        int g = c >> 4;
        int jl = c & 15;
        int colH = (g < 2) ? (g * 512 + jg * 16 + jl) : (1536 + jg * 16 + jl);
        int s = k * C4H + colH;
        g_wt2[jj] = whh_mu[s] + softplusf_(whh_rho[s]) * eps_hh[s];
    } else if (i < N3) {
        int jj = i - N2;
        g_bias[jj] = b_mu[jj] + softplusf_(b_rho[jj]) * eps_b[jj];
    } else if (i < N4) {
        g_bar[i - N3] = 0u;
    }
}

// ---------------- xg GEMM: C[m][c] = sum_k x[m][k] * g_wih[k][c] ----------------
#define GM 32768
#define GN 1536
#define GK 512
#define BKk 16

__global__ __launch_bounds__(256, 2) void xg_gemm_kernel(const float* __restrict__ A) {
    __shared__ float As[2][BKk][128];
    __shared__ float Bs[2][BKk][128];

    const int tid = threadIdx.x;
    const int bx = blockIdx.x;
    const int by = blockIdx.y;

    const float* Ab = A + (size_t)by * 128 * GK;
    const float* Bb = g_wih + bx * 128;

    const int aRow  = tid >> 1;
    const int aColH = (tid & 1) * 8;
    const int bKr = tid >> 4;
    const int bC  = (tid & 15) * 8;

    const int tx = tid & 15;
    const int ty = tid >> 4;

    float acc[8][8];
#pragma unroll
    for (int i = 0; i < 8; i++)
#pragma unroll
        for (int j = 0; j < 8; j++) acc[i][j] = 0.f;

    float4 a0, a1, b0, b1;
    a0 = *(const float4*)&Ab[(size_t)aRow * GK + aColH];
    a1 = *(const float4*)&Ab[(size_t)aRow * GK + aColH + 4];
    b0 = *(const float4*)&Bb[(size_t)bKr * GN + bC];
    b1 = *(const float4*)&Bb[(size_t)bKr * GN + bC + 4];
    {
        float av[8] = {a0.x, a0.y, a0.z, a0.w, a1.x, a1.y, a1.z, a1.w};
#pragma unroll
        for (int i = 0; i < 8; i++) As[0][aColH + i][aRow] = av[i];
        *(float4*)&Bs[0][bKr][bC] = b0;
        *(float4*)&Bs[0][bKr][bC + 4] = b1;
    }
    __syncthreads();

    for (int k0 = 0; k0 < GK; k0 += BKk) {
        const int buf = (k0 / BKk) & 1;
        const bool more = (k0 + BKk) < GK;
        if (more) {
            a0 = *(const float4*)&Ab[(size_t)aRow * GK + k0 + BKk + aColH];
            a1 = *(const float4*)&Ab[(size_t)aRow * GK + k0 + BKk + aColH + 4];
            b0 = *(const float4*)&Bb[(size_t)(k0 + BKk + bKr) * GN + bC];
            b1 = *(const float4*)&Bb[(size_t)(k0 + BKk + bKr) * GN + bC + 4];
        }
#pragma unroll
        for (int kk = 0; kk < BKk; kk++) {
            float ar[8], br[8];
            *(float4*)&ar[0] = *(const float4*)&As[buf][kk][ty * 4];
            *(float4*)&ar[4] = *(const float4*)&As[buf][kk][64 + ty * 4];
            *(float4*)&br[0] = *(const float4*)&Bs[buf][kk][tx * 4];
            *(float4*)&br[4] = *(const float4*)&Bs[buf][kk][64 + tx * 4];
#pragma unroll
            for (int i = 0; i < 8; i++)
#pragma unroll
                for (int j = 0; j < 8; j++) acc[i][j] += ar[i] * br[j];
        }
        if (more) {
            const int nbuf = buf ^ 1;
            float av[8] = {a0.x, a0.y, a0.z, a0.w, a1.x, a1.y, a1.z, a1.w};
#pragma unroll
            for (int i = 0; i < 8; i++) As[nbuf][aColH + i][aRow] = av[i];
            *(float4*)&Bs[nbuf][bKr][bC] = b0;
            *(float4*)&Bs[nbuf][bKr][bC + 4] = b1;
            __syncthreads();
        }
    }

    // epilogue: scatter to scan-tiled layout g_xg[t][bg][jg][b8][48]
#pragma unroll
    for (int i = 0; i < 8; i++) {
        int row = (i < 4) ? (ty * 4 + i) : (64 + ty * 4 + (i - 4));
        int m = by * 128 + row;
        int b = m >> 10;
        int t = m & 1023;
        int bg = b >> 3, b8 = b & 7;
        size_t base = ((((size_t)t * 4 + bg) * 32) * 8) * 48;  // + jg*8*48 later
#pragma unroll
        for (int half = 0; half < 2; half++) {
            int cc = half ? (64 + tx * 4) : (tx * 4);
            int c = bx * 128 + cc;
            int g = c >> 9;
            int jdx = c & 511;
            int jgp = jdx >> 4;
            int jl = jdx & 15;
            int col = g * 16 + jl;
            size_t off = base + ((size_t)jgp * 8 + b8) * 48 + col;
            float4 v = half ? make_float4(acc[i][4], acc[i][5], acc[i][6], acc[i][7])
                            : make_float4(acc[i][0], acc[i][1], acc[i][2], acc[i][3]);
            *(float4*)&g_xg[off] = v;
        }
    }
}

// ---------------- persistent GRU scan ----------------
// 128 CTAs = 4 batch-groups (8 b) x 32 j-groups (16 j). Weights resident in smem.
#define SK_W  52   // padded row stride for w[k][c]
#define SK_HP 12   // padded row stride for h[k][b]

struct ScanSmem {
    float w[512 * SK_W];        // 106496 B
    float h[512 * SK_HP];       // 24576 B
    float part[8 * 16 * 3 * 10];// 15360 B
};

__global__ __launch_bounds__(256, 1) void scan_kernel(const float* __restrict__ h0,
                                                      float* __restrict__ out,
                                                      int write_last) {
    extern __shared__ float smem_raw[];
    ScanSmem* S = (ScanSmem*)smem_raw;

    const int tid = threadIdx.x;
    const int bg = blockIdx.x >> 5;
    const int jg = blockIdx.x & 31;
    const int j = tid & 15;
    const int ks = tid >> 4;       // 16 k-slices of 32
    const int wid = tid >> 5;
    const int lane = tid & 31;
    const int fb = tid >> 4;       // final-stage b (tid<128)
    const int jgl = jg * 16 + j;

    // load this CTA's 48 weight columns, k-major
    {
        const float* wb = g_wt2 + (size_t)jg * 24576;
        for (int q = tid; q < 6144; q += 256) {
            int k = q / 12, c4 = (q % 12) * 4;
            float4 v = *(const float4*)&wb[k * 48 + c4];
            *(float4*)&S->w[k * SK_W + c4] = v;
        }
    }
    float b_r = 0.f, b_z = 0.f, b_n = 0.f, b_hn = 0.f;
    if (tid < 128) {
        b_r  = g_bias[jgl];
        b_z  = g_bias[512 + jgl];
        b_n  = g_bias[1024 + jgl];
        b_hn = g_bias[1536 + jgl];
    }
    __syncthreads();

    for (int t = 0; t < Tlen; t++) {
        // xg prefetch (independent of barrier/h)
        float xr = 0.f, xz = 0.f, xn = 0.f;
        if (tid < 128) {
            const float* xp = g_xg + ((((size_t)t * 4 + bg) * 32 + jg) * 8 + fb) * 48;
            xr = xp[j]; xz = xp[16 + j]; xn = xp[32 + j];
        }

        // load 8 h rows (16KB), transpose into h[k][b]
        const float* hsrc = (t == 0) ? (h0 + (size_t)bg * 8 * 512)
                                     : (&g_h[t & 1][bg * 8 * 512]);
        float4 v[4];
#pragma unroll
        for (int i = 0; i < 4; i++) {
            int q = tid + 256 * i;
            int b8 = q >> 7, kq = (q & 127) << 2;
            v[i] = __ldcg((const float4*)&hsrc[b8 * 512 + kq]);
        }
#pragma unroll
        for (int i = 0; i < 4; i++) {
            int q = tid + 256 * i;
            int b8 = q >> 7, kq = (q & 127) << 2;
            S->h[(kq + 0) * SK_HP + b8] = v[i].x;
            S->h[(kq + 1) * SK_HP + b8] = v[i].y;
            S->h[(kq + 2) * SK_HP + b8] = v[i].z;
            S->h[(kq + 3) * SK_HP + b8] = v[i].w;
        }
        __syncthreads();

        // partial dots: tile 8b x 3g, k-slice of 32, f32x2 over b-pairs
        unsigned long long acc[3][4];
#pragma unroll
        for (int g = 0; g < 3; g++)
#pragma unroll
            for (int p = 0; p < 4; p++) acc[g][p] = 0ull;

        const int k0 = ks * 32;
#pragma unroll 4
        for (int kk = 0; kk < 32; kk++) {
            int k = k0 + kk;
            const float* hp = &S->h[k * SK_HP];
            ulonglong2 hA = *(const ulonglong2*)(hp);       // b0..3
            ulonglong2 hB = *(const ulonglong2*)(hp + 4);   // b4..7
            const float* wp = &S->w[k * SK_W];
            unsigned long long wr = pack2(wp[j]);
            unsigned long long wz = pack2(wp[16 + j]);
            unsigned long long wn = pack2(wp[32 + j]);
            fma2(acc[0][0], hA.x, wr); fma2(acc[0][1], hA.y, wr);
            fma2(acc[0][2], hB.x, wr); fma2(acc[0][3], hB.y, wr);
            fma2(acc[1][0], hA.x, wz); fma2(acc[1][1], hA.y, wz);
            fma2(acc[1][2], hB.x, wz); fma2(acc[1][3], hB.y, wz);
            fma2(acc[2][0], hA.x, wn); fma2(acc[2][1], hA.y, wn);
            fma2(acc[2][2], hB.x, wn); fma2(acc[2][3], hB.y, wn);
        }

        // reduce ks pair within warp
#pragma unroll
        for (int g = 0; g < 3; g++)
#pragma unroll
            for (int p = 0; p < 4; p++) {
                unsigned long long o = __shfl_xor_sync(0xffffffffu, acc[g][p], 16);
                acc[g][p] = add2(acc[g][p], o);
            }
        if (lane < 16) {
#pragma unroll
            for (int g = 0; g < 3; g++)
#pragma unroll
                for (int p = 0; p < 4; p++)
                    *(unsigned long long*)&S->part[(((wid * 16 + j) * 3 + g) * 5 + p) * 2] = acc[g][p];
        }
        __syncthreads();

        // final: 8-warp reduce + gates + writes
        if (tid < 128) {
            float sr = 0.f, sz = 0.f, sn = 0.f;
#pragma unroll
            for (int w = 0; w < 8; w++) {
                const float* pp = &S->part[((w * 16 + j) * 3) * 10 + fb];
                sr += pp[0];
                sz += pp[10];
                sn += pp[20];
            }
            float r = 1.f / (1.f + __expf(-(sr + xr + b_r)));
            float z = 1.f / (1.f + __expf(-(sz + xz + b_z)));
            float n = tanhf(xn + b_n + r * (sn + b_hn));
            float hprev = S->h[jgl * SK_HP + fb];
            float hnew = (1.f - z) * n + z * hprev;
            g_h[(t + 1) & 1][(bg * 8 + fb) * 512 + jgl] = hnew;
            out[((size_t)(bg * 8 + fb) * 1024 + t) * 512 + jgl] = hnew;
            if (write_last && t == Tlen - 1)
                out[(size_t)Bsz * Tlen * Hh + (bg * 8 + fb) * 512 + jgl] = hnew;
        }

        // per-batch-group barrier (32 CTAs)
        if (t < Tlen - 1) {
            __syncthreads();
            if (tid == 0) {
                unsigned* bp = &g_bar[bg * Tlen + t];
                asm volatile("red.release.gpu.global.add.u32 [%0], %1;"
                             :: "l"(bp), "r"(1u) : "memory");
                unsigned vv;
                do {
                    asm volatile("ld.acquire.gpu.global.u32 %0, [%1];"
                                 : "=r"(vv) : "l"(bp) : "memory");
                } while (vv < 32u);
            }
            __syncthreads();
        }
    }
}

// ---------------- launch ----------------
extern "C" void kernel_launch(void* const* d_in, const int* in_sizes, int n_in,
                              void* d_out, int out_size) {
    const float* x       = (const float*)d_in[0];
    const float* h0      = (const float*)d_in[1];
    const float* wih_mu  = (const float*)d_in[2];
    const float* wih_rho = (const float*)d_in[3];
    const float* whh_mu  = (const float*)d_in[4];
    const float* whh_rho = (const float*)d_in[5];
    const float* b_mu    = (const float*)d_in[6];
    const float* b_rho   = (const float*)d_in[7];
    const float* eps_ih  = (const float*)d_in[8];
    const float* eps_hh  = (const float*)d_in[9];
    const float* eps_b   = (const float*)d_in[10];
    float* out = (float*)d_out;

    {
        int total = Dd * NG + 32 * 512 * 48 + C4H + 4 * Tlen;
        int blocks = (total + 255) / 256;
        sample_all_kernel<<<blocks, 256>>>(wih_mu, wih_rho, eps_ih,
                                           whh_mu, whh_rho, eps_hh,
                                           b_mu, b_rho, eps_b);
    }
    {
        dim3 grid(GN / 128, GM / 128);
        xg_gemm_kernel<<<grid, 256>>>(x);
    }
    {
        int smem = (int)sizeof(ScanSmem);
        cudaFuncSetAttribute(scan_kernel, cudaFuncAttributeMaxDynamicSharedMemorySize, smem);
        int write_last = (out_size >= Bsz * Tlen * Hh + Bsz * Hh) ? 1 : 0;
        scan_kernel<<<128, 256, smem>>>(h0, out, write_last);
    }
}

// round 5
// speedup vs baseline: 1.6504x; 1.1389x over previous
#include <cuda_runtime.h>
#include <math.h>

// Problem constants
#define Bsz  32
#define Tlen 1024
#define Dd   512
#define Hh   512
#define NG   1536   // 3*H
#define C4H  2048   // 4*H

// -------- device scratch --------
__device__ float g_wih[Dd * NG];                 // sampled w_ih[:, :3H], [d][c]
__device__ float g_wt2[32 * 512 * 48];           // scan weights [jg][k][c], c = g*16+jl
__device__ float g_bias[C4H];
__device__ float g_xg[(size_t)Bsz * Tlen * NG];  // [t][bg][jg][b8][48]
__device__ float g_ht[2][4][512 * 8];            // ping-pong hidden, transposed [bg][k][b8]
__device__ unsigned g_bar[4 * Tlen];             // per-batch-group barrier counters

__device__ __forceinline__ float softplusf_(float x) {
    return x > 20.f ? x : log1pf(__expf(x));
}

// f32x2 helpers
typedef unsigned long long ull;
__device__ __forceinline__ ull pack2(float x) {
    ull d; unsigned u = __float_as_uint(x);
    asm("mov.b64 %0, {%1, %1};" : "=l"(d) : "r"(u));
    return d;
}
__device__ __forceinline__ void fma2(ull& d, ull a, ull b) {
    asm("fma.rn.f32x2 %0, %1, %2, %0;" : "+l"(d) : "l"(a), "l"(b));
}
__device__ __forceinline__ ull add2(ull a, ull b) {
    ull d;
    asm("add.rn.f32x2 %0, %1, %2;" : "=l"(d) : "l"(a), "l"(b));
    return d;
}
__device__ __forceinline__ void unpack2(ull d, float& lo, float& hi) {
    unsigned a, b;
    asm("mov.b64 {%0, %1}, %2;" : "=r"(a), "=r"(b) : "l"(d));
    lo = __uint_as_float(a); hi = __uint_as_float(b);
}

// ---------------- prologue: sample weights + reset barriers ----------------
__global__ void sample_all_kernel(const float* __restrict__ wih_mu, const float* __restrict__ wih_rho,
                                  const float* __restrict__ eps_ih,
                                  const float* __restrict__ whh_mu, const float* __restrict__ whh_rho,
                                  const float* __restrict__ eps_hh,
                                  const float* __restrict__ b_mu, const float* __restrict__ b_rho,
                                  const float* __restrict__ eps_b) {
    int i = blockIdx.x * blockDim.x + threadIdx.x;
    const int N1 = Dd * NG;
    const int N2 = N1 + 32 * 512 * 48;
    const int N3 = N2 + C4H;
    const int N4 = N3 + 4 * Tlen;
    if (i < N1) {
        int d = i / NG, c = i % NG;
        int s = d * C4H + c;
        g_wih[i] = wih_mu[s] + softplusf_(wih_rho[s]) * eps_ih[s];
    } else if (i < N2) {
        int jj = i - N1;
        int jg = jj / 24576;
        int r = jj % 24576;
        int k = r / 48;
        int c = r % 48;
        int g = c >> 4;
        int jl = c & 15;
        int colH = (g < 2) ? (g * 512 + jg * 16 + jl) : (1536 + jg * 16 + jl);
        int s = k * C4H + colH;
        g_wt2[jj] = whh_mu[s] + softplusf_(whh_rho[s]) * eps_hh[s];
    } else if (i < N3) {
        int jj = i - N2;
        g_bias[jj] = b_mu[jj] + softplusf_(b_rho[jj]) * eps_b[jj];
    } else if (i < N4) {
        g_bar[i - N3] = 0u;
    }
}

// ---------------- xg GEMM with packed f32x2 FMA ----------------
#define GM 32768
#define GN 1536
#define GK 512
#define BKk 16

__global__ __launch_bounds__(256, 2) void xg_gemm_kernel(const float* __restrict__ A) {
    __shared__ float As2[2][BKk][256];   // A tile, each value duplicated: [kk][2*row+{0,1}]
    __shared__ float Bs[2][BKk][128];

    const int tid = threadIdx.x;
    const int bx = blockIdx.x;
    const int by = blockIdx.y;

    const float* Ab = A + (size_t)by * 128 * GK;
    const float* Bb = g_wih + bx * 128;

    const int aRow  = tid >> 1;
    const int aColH = (tid & 1) * 8;
    const int bKr = tid >> 4;
    const int bC  = (tid & 15) * 8;

    const int tx = tid & 15;
    const int ty = tid >> 4;

    ull acc[8][4];
#pragma unroll
    for (int i = 0; i < 8; i++)
#pragma unroll
        for (int j = 0; j < 4; j++) acc[i][j] = 0ull;

    float4 a0, a1, b0, b1;
    a0 = *(const float4*)&Ab[(size_t)aRow * GK + aColH];
    a1 = *(const float4*)&Ab[(size_t)aRow * GK + aColH + 4];
    b0 = *(const float4*)&Bb[(size_t)bKr * GN + bC];
    b1 = *(const float4*)&Bb[(size_t)bKr * GN + bC + 4];
    {
        float av[8] = {a0.x, a0.y, a0.z, a0.w, a1.x, a1.y, a1.z, a1.w};
#pragma unroll
        for (int i = 0; i < 8; i++)
            *(float2*)&As2[0][aColH + i][2 * aRow] = make_float2(av[i], av[i]);
        *(float4*)&Bs[0][bKr][bC] = b0;
        *(float4*)&Bs[0][bKr][bC + 4] = b1;
    }
    __syncthreads();

    for (int k0 = 0; k0 < GK; k0 += BKk) {
        const int buf = (k0 / BKk) & 1;
        const bool more = (k0 + BKk) < GK;
        if (more) {
            a0 = *(const float4*)&Ab[(size_t)aRow * GK + k0 + BKk + aColH];
            a1 = *(const float4*)&Ab[(size_t)aRow * GK + k0 + BKk + aColH + 4];
            b0 = *(const float4*)&Bb[(size_t)(k0 + BKk + bKr) * GN + bC];
            b1 = *(const float4*)&Bb[(size_t)(k0 + BKk + bKr) * GN + bC + 4];
        }
#pragma unroll
        for (int kk = 0; kk < BKk; kk++) {
            ulonglong2 arA = *(const ulonglong2*)&As2[buf][kk][2 * (ty * 4)];
            ulonglong2 arB = *(const ulonglong2*)&As2[buf][kk][2 * (ty * 4) + 4];
            ulonglong2 arC = *(const ulonglong2*)&As2[buf][kk][2 * (64 + ty * 4)];
            ulonglong2 arD = *(const ulonglong2*)&As2[buf][kk][2 * (64 + ty * 4) + 4];
            ulonglong2 brA = *(const ulonglong2*)&Bs[buf][kk][tx * 4];
            ulonglong2 brB = *(const ulonglong2*)&Bs[buf][kk][64 + tx * 4];
            ull ar2[8] = {arA.x, arA.y, arB.x, arB.y, arC.x, arC.y, arD.x, arD.y};
            ull br2[4] = {brA.x, brA.y, brB.x, brB.y};
#pragma unroll
            for (int i = 0; i < 8; i++)
#pragma unroll
                for (int jp = 0; jp < 4; jp++) fma2(acc[i][jp], ar2[i], br2[jp]);
        }
        if (more) {
            const int nbuf = buf ^ 1;
            float av[8] = {a0.x, a0.y, a0.z, a0.w, a1.x, a1.y, a1.z, a1.w};
#pragma unroll
            for (int i = 0; i < 8; i++)
                *(float2*)&As2[nbuf][aColH + i][2 * aRow] = make_float2(av[i], av[i]);
            *(float4*)&Bs[nbuf][bKr][bC] = b0;
            *(float4*)&Bs[nbuf][bKr][bC + 4] = b1;
            __syncthreads();
        }
    }

    // epilogue: scatter to scan-tiled layout g_xg[t][bg][jg][b8][48]
#pragma unroll
    for (int i = 0; i < 8; i++) {
        int row = (i < 4) ? (ty * 4 + i) : (64 + ty * 4 + (i - 4));
        int m = by * 128 + row;
        int b = m >> 10;
        int t = m & 1023;
        int bg = b >> 3, b8 = b & 7;
        size_t base = ((((size_t)t * 4 + bg) * 32) * 8) * 48;
#pragma unroll
        for (int half = 0; half < 2; half++) {
            int cc = half ? (64 + tx * 4) : (tx * 4);
            int c = bx * 128 + cc;
            int g = c >> 9;
            int jdx = c & 511;
            int jgp = jdx >> 4;
            int jl = jdx & 15;
            int col = g * 16 + jl;
            size_t off = base + ((size_t)jgp * 8 + b8) * 48 + col;
            float4 v;
            if (half) {
                unpack2(acc[i][2], v.x, v.y); unpack2(acc[i][3], v.z, v.w);
            } else {
                unpack2(acc[i][0], v.x, v.y); unpack2(acc[i][1], v.z, v.w);
            }
            *(float4*)&g_xg[off] = v;
        }
    }
}

// ---------------- persistent GRU scan ----------------
// 128 CTAs = 4 batch-groups (8 b) x 32 j-groups (16 j). Weights resident in smem.
#define SK_W 52

struct ScanSmem {
    float w[512 * SK_W];        // 106496 B
    float h[512 * 8];           // 16384 B, [k][b8]
    float part[8 * 16 * 3 * 10];// 15360 B
};

__global__ __launch_bounds__(256, 1) void scan_kernel(const float* __restrict__ h0,
                                                      float* __restrict__ out,
                                                      int write_last) {
    extern __shared__ float smem_raw[];
    ScanSmem* S = (ScanSmem*)smem_raw;

    const int tid = threadIdx.x;
    const int bg = blockIdx.x >> 5;
    const int jg = blockIdx.x & 31;
    const int j = tid & 15;
    const int ks = tid >> 4;
    const int wid = tid >> 5;
    const int lane = tid & 31;
    const int fb = tid >> 4;       // final-stage b (tid<128)
    const int jgl = jg * 16 + j;

    // load this CTA's 48 weight columns, k-major
    {
        const float* wb = g_wt2 + (size_t)jg * 24576;
        for (int q = tid; q < 6144; q += 256) {
            int k = q / 12, c4 = (q % 12) * 4;
            float4 v = *(const float4*)&wb[k * 48 + c4];
            *(float4*)&S->w[k * SK_W + c4] = v;
        }
    }
    float b_r = 0.f, b_z = 0.f, b_n = 0.f, b_hn = 0.f;
    float xr = 0.f, xz = 0.f, xn = 0.f;
    if (tid < 128) {
        b_r  = g_bias[jgl];
        b_z  = g_bias[512 + jgl];
        b_n  = g_bias[1024 + jgl];
        b_hn = g_bias[1536 + jgl];
        const float* xp = g_xg + (((size_t)0 * 4 + bg) * 32 + jg) * 8 * 48 + fb * 48;
        xr = xp[j]; xz = xp[16 + j]; xn = xp[32 + j];
    }
    __syncthreads();

    for (int t = 0; t < Tlen; t++) {
        // ---- bring h(t) into smem [k][b8] ----
        if (t == 0) {
            const float* hsrc = h0 + (size_t)bg * 8 * 512;
            for (int q = tid; q < 1024; q += 256) {
                int b8 = q >> 7, kq = (q & 127) << 2;
                float4 v = *(const float4*)&hsrc[b8 * 512 + kq];
                S->h[(kq + 0) * 8 + b8] = v.x;
                S->h[(kq + 1) * 8 + b8] = v.y;
                S->h[(kq + 2) * 8 + b8] = v.z;
                S->h[(kq + 3) * 8 + b8] = v.w;
            }
        } else {
            const float* hsrc = &g_ht[t & 1][bg][0];
#pragma unroll
            for (int i = 0; i < 4; i++) {
                int q = (tid + 256 * i) << 2;
                float4 v = __ldcg((const float4*)&hsrc[q]);
                *(float4*)&S->h[q] = v;
            }
        }
        __syncthreads();

        // ---- partial dots: tile 8b x 3g, k-slice of 32, f32x2 over b-pairs ----
        ull acc[3][4];
#pragma unroll
        for (int g = 0; g < 3; g++)
#pragma unroll
            for (int p = 0; p < 4; p++) acc[g][p] = 0ull;

        const int k0 = ks * 32;
#pragma unroll 4
        for (int kk = 0; kk < 32; kk++) {
            int k = k0 + kk;
            const float* hp = &S->h[k * 8];
            ulonglong2 hA = *(const ulonglong2*)(hp);
            ulonglong2 hB = *(const ulonglong2*)(hp + 4);
            const float* wp = &S->w[k * SK_W];
            ull wr = pack2(wp[j]);
            ull wz = pack2(wp[16 + j]);
            ull wn = pack2(wp[32 + j]);
            fma2(acc[0][0], hA.x, wr); fma2(acc[0][1], hA.y, wr);
            fma2(acc[0][2], hB.x, wr); fma2(acc[0][3], hB.y, wr);
            fma2(acc[1][0], hA.x, wz); fma2(acc[1][1], hA.y, wz);
            fma2(acc[1][2], hB.x, wz); fma2(acc[1][3], hB.y, wz);
            fma2(acc[2][0], hA.x, wn); fma2(acc[2][1], hA.y, wn);
            fma2(acc[2][2], hB.x, wn); fma2(acc[2][3], hB.y, wn);
        }

#pragma unroll
        for (int g = 0; g < 3; g++)
#pragma unroll
            for (int p = 0; p < 4; p++) {
                ull o = __shfl_xor_sync(0xffffffffu, acc[g][p], 16);
                acc[g][p] = add2(acc[g][p], o);
            }
        if (lane < 16) {
#pragma unroll
            for (int g = 0; g < 3; g++)
#pragma unroll
                for (int p = 0; p < 4; p++)
                    *(ull*)&S->part[(((wid * 16 + j) * 3 + g) * 5 + p) * 2] = acc[g][p];
        }
        __syncthreads();

        // ---- final: 8-warp reduce + gates + h store ----
        float hnew = 0.f;
        if (tid < 128) {
            float sr = 0.f, sz = 0.f, sn = 0.f;
#pragma unroll
            for (int w = 0; w < 8; w++) {
                const float* pp = &S->part[((w * 16 + j) * 3) * 10 + fb];
                sr += pp[0];
                sz += pp[10];
                sn += pp[20];
            }
            float r = 1.f / (1.f + __expf(-(sr + xr + b_r)));
            float z = 1.f / (1.f + __expf(-(sz + xz + b_z)));
            float n = tanhf(xn + b_n + r * (sn + b_hn));
            float hprev = S->h[jgl * 8 + fb];
            hnew = (1.f - z) * n + z * hprev;
            g_ht[(t + 1) & 1][bg][jgl * 8 + fb] = hnew;
        }

        if (t < Tlen - 1) {
            __syncthreads();   // all h stores issued (and smem reads of this step done)
            if (tid == 0) {
                unsigned* bp = &g_bar[bg * Tlen + t];
                asm volatile("red.release.gpu.global.add.u32 [%0], %1;"
                             :: "l"(bp), "r"(1u) : "memory");
            }
            // ---- shadow work while the barrier settles ----
            if (tid < 128) {
                out[((size_t)(bg * 8 + fb) * 1024 + t) * 512 + jgl] = hnew;
                const float* xp = g_xg + ((((size_t)(t + 1) * 4 + bg) * 32 + jg) * 8 + fb) * 48;
                xr = xp[j]; xz = xp[16 + j]; xn = xp[32 + j];
            }
            if (tid == 0) {
                unsigned* bp = &g_bar[bg * Tlen + t];
                unsigned vv;
                do {
                    asm volatile("ld.acquire.gpu.global.u32 %0, [%1];"
                                 : "=r"(vv) : "l"(bp) : "memory");
                } while (vv < 32u);
            }
            __syncthreads();
        } else {
            if (tid < 128) {
                out[((size_t)(bg * 8 + fb) * 1024 + t) * 512 + jgl] = hnew;
                if (write_last)
                    out[(size_t)Bsz * Tlen * Hh + (bg * 8 + fb) * 512 + jgl] = hnew;
            }
        }
    }
}

// ---------------- launch ----------------
extern "C" void kernel_launch(void* const* d_in, const int* in_sizes, int n_in,
                              void* d_out, int out_size) {
    const float* x       = (const float*)d_in[0];
    const float* h0      = (const float*)d_in[1];
    const float* wih_mu  = (const float*)d_in[2];
    const float* wih_rho = (const float*)d_in[3];
    const float* whh_mu  = (const float*)d_in[4];
    const float* whh_rho = (const float*)d_in[5];
    const float* b_mu    = (const float*)d_in[6];
    const float* b_rho   = (const float*)d_in[7];
    const float* eps_ih  = (const float*)d_in[8];
    const float* eps_hh  = (const float*)d_in[9];
    const float* eps_b   = (const float*)d_in[10];
    float* out = (float*)d_out;

    {
        int total = Dd * NG + 32 * 512 * 48 + C4H + 4 * Tlen;
        int blocks = (total + 255) / 256;
        sample_all_kernel<<<blocks, 256>>>(wih_mu, wih_rho, eps_ih,
                                           whh_mu, whh_rho, eps_hh,
                                           b_mu, b_rho, eps_b);
    }
    {
        dim3 grid(GN / 128, GM / 128);
        xg_gemm_kernel<<<grid, 256>>>(x);
    }
    {
        int smem = (int)sizeof(ScanSmem);
        cudaFuncSetAttribute(scan_kernel, cudaFuncAttributeMaxDynamicSharedMemorySize, smem);
        int write_last = (out_size >= Bsz * Tlen * Hh + Bsz * Hh) ? 1 : 0;
        scan_kernel<<<128, 256, smem>>>(h0, out, write_last);
    }
}

// round 7
// speedup vs baseline: 1.9136x; 1.1594x over previous
#include <cuda_runtime.h>
#include <math.h>

// Problem constants
#define Bsz  32
#define Tlen 1024
#define Dd   512
#define Hh   512
#define NG   1536   // 3*H
#define C4H  2048   // 4*H

// -------- device scratch --------
__device__ float g_wih[Dd * NG];                 // sampled w_ih[:, :3H], [d][c]
__device__ float g_wt2[32 * 512 * 48];           // scan weights [jg][k][c], c = g*16+jl
__device__ float g_bias[C4H];
__device__ float g_xt[(size_t)4 * Tlen * 512 * 8]; // x transposed: [bg][t][k][b8]
__device__ float g_ht[2][4][512 * 8];            // ping-pong hidden, transposed [bg][k][b8]
__device__ unsigned g_bar[4 * Tlen];             // per-batch-group barrier counters

__device__ __forceinline__ float softplusf_(float x) {
    return x > 20.f ? x : log1pf(__expf(x));
}

typedef unsigned long long ull;
__device__ __forceinline__ ull pack2(float x) {
    ull d; unsigned u = __float_as_uint(x);
    asm("mov.b64 %0, {%1, %1};" : "=l"(d) : "r"(u));
    return d;
}
__device__ __forceinline__ void fma2(ull& d, ull a, ull b) {
    asm("fma.rn.f32x2 %0, %1, %2, %0;" : "+l"(d) : "l"(a), "l"(b));
}
__device__ __forceinline__ ull add2(ull a, ull b) {
    ull d;
    asm("add.rn.f32x2 %0, %1, %2;" : "=l"(d) : "l"(a), "l"(b));
    return d;
}

// ---------------- prologue: sample weights + reset barriers ----------------
__global__ void sample_all_kernel(const float* __restrict__ wih_mu, const float* __restrict__ wih_rho,
                                  const float* __restrict__ eps_ih,
                                  const float* __restrict__ whh_mu, const float* __restrict__ whh_rho,
                                  const float* __restrict__ eps_hh,
                                  const float* __restrict__ b_mu, const float* __restrict__ b_rho,
                                  const float* __restrict__ eps_b) {
    int i = blockIdx.x * blockDim.x + threadIdx.x;
    const int N1 = Dd * NG;
    const int N2 = N1 + 32 * 512 * 48;
    const int N3 = N2 + C4H;
    const int N4 = N3 + 4 * Tlen;
    if (i < N1) {
        int d = i / NG, c = i % NG;
        int s = d * C4H + c;
        g_wih[i] = wih_mu[s] + softplusf_(wih_rho[s]) * eps_ih[s];
    } else if (i < N2) {
        int jj = i - N1;
        int jg = jj / 24576;
        int r = jj % 24576;
        int k = r / 48;
        int c = r % 48;
        int g = c >> 4;
        int jl = c & 15;
        int colH = (g < 2) ? (g * 512 + jg * 16 + jl) : (1536 + jg * 16 + jl);
        int s = k * C4H + colH;
        g_wt2[jj] = whh_mu[s] + softplusf_(whh_rho[s]) * eps_hh[s];
    } else if (i < N3) {
        int jj = i - N2;
        g_bias[jj] = b_mu[jj] + softplusf_(b_rho[jj]) * eps_b[jj];
    } else if (i < N4) {
        g_bar[i - N3] = 0u;
    }
}

// ---------------- x transpose: x[b][t][d] -> xT[bg][t][k][b8] ----------------
__global__ __launch_bounds__(256) void xpose_kernel(const float* __restrict__ x) {
    int idx = blockIdx.x * 256 + threadIdx.x;      // 4*1024*128*8 = 4194304
    int b8 = idx & 7;
    int k4 = (idx >> 3) & 127;
    int t  = (idx >> 10) & 1023;
    int bg = idx >> 20;
    float4 v = *(const float4*)&x[((size_t)(bg * 8 + b8) * 1024 + t) * 512 + k4 * 4];
    size_t base = ((size_t)(bg * 1024 + t) * 512) * 8;
    g_xt[base + (size_t)(k4 * 4 + 0) * 8 + b8] = v.x;
    g_xt[base + (size_t)(k4 * 4 + 1) * 8 + b8] = v.y;
    g_xt[base + (size_t)(k4 * 4 + 2) * 8 + b8] = v.z;
    g_xt[base + (size_t)(k4 * 4 + 3) * 8 + b8] = v.w;
}

// ---------------- fused persistent GRU scan + input GEMM ----------------
// 128 CTAs = 4 batch-groups (8 b) x 32 j-groups (16 j).
// w_hh in smem; w_ih slice in registers; xg never touches global memory.
#define SK_W 52

struct ScanSmem {
    float w[512 * SK_W];        // 106496 B
    float h[512 * 8];           // 16384 B, [k][b8]
    float x[2][512 * 8];        // 32768 B, [k][b8]
    float part[8 * 16 * 3 * 10];// 15360 B
};

__global__ __launch_bounds__(256, 1) void scan_kernel(const float* __restrict__ h0,
                                                      float* __restrict__ out,
                                                      int write_last) {
    extern __shared__ float smem_raw[];
    ScanSmem* S = (ScanSmem*)smem_raw;

    const int tid = threadIdx.x;
    const int bg = blockIdx.x >> 5;
    const int jg = blockIdx.x & 31;
    const int j = tid & 15;
    const int ks = tid >> 4;
    const int k0 = ks * 32;
    const int wid = tid >> 5;
    const int lane = tid & 31;
    const int fb = tid >> 4;       // final-stage b (tid<128)
    const int jgl = jg * 16 + j;

    // ---- w_hh columns into smem ----
    {
        const float* wb = g_wt2 + (size_t)jg * 24576;
        for (int q = tid; q < 6144; q += 256) {
            int k = q / 12, c4 = (q % 12) * 4;
            float4 v = *(const float4*)&wb[k * 48 + c4];
            *(float4*)&S->w[k * SK_W + c4] = v;
        }
    }
    // ---- w_ih slice into registers (constant for whole scan) ----
    float wr_ih[32], wz_ih[32], wn_ih[32];
    {
        const float* p = g_wih + (size_t)k0 * NG + (jg * 16 + j);
#pragma unroll
        for (int kk = 0; kk < 32; kk++) {
            wr_ih[kk] = __ldg(&p[kk * NG]);
            wz_ih[kk] = __ldg(&p[kk * NG + 512]);
            wn_ih[kk] = __ldg(&p[kk * NG + 1024]);
        }
    }
    float b_r = 0.f, b_z = 0.f, b_n = 0.f, b_hn = 0.f;
    if (tid < 128) {
        b_r  = g_bias[jgl];
        b_z  = g_bias[512 + jgl];
        b_n  = g_bias[1024 + jgl];
        b_hn = g_bias[1536 + jgl];
    }

    // ---- stage x(0) into xbuf[1] (temp) ----
    {
        const float* xsrc = g_xt + ((size_t)(bg * 1024 + 0) * 512) * 8;
#pragma unroll
        for (int i = 0; i < 4; i++) {
            int q = (tid + 256 * i) << 2;
            float4 v = __ldg((const float4*)&xsrc[q]);
            *(float4*)&S->x[1][q] = v;
        }
    }
    __syncthreads();

    // ---- compute xg(0) into regs ----
    float xr = 0.f, xz = 0.f, xn = 0.f;
    {
        ull acc[3][4];
#pragma unroll
        for (int g = 0; g < 3; g++)
#pragma unroll
            for (int p = 0; p < 4; p++) acc[g][p] = 0ull;
        const float* xp = &S->x[1][0];
#pragma unroll
        for (int kk = 0; kk < 32; kk++) {
            int k = k0 + kk;
            ulonglong2 hA = *(const ulonglong2*)&xp[k * 8];
            ulonglong2 hB = *(const ulonglong2*)&xp[k * 8 + 4];
            ull wr = pack2(wr_ih[kk]);
            ull wz = pack2(wz_ih[kk]);
            ull wn = pack2(wn_ih[kk]);
            fma2(acc[0][0], hA.x, wr); fma2(acc[0][1], hA.y, wr);
            fma2(acc[0][2], hB.x, wr); fma2(acc[0][3], hB.y, wr);
            fma2(acc[1][0], hA.x, wz); fma2(acc[1][1], hA.y, wz);
            fma2(acc[1][2], hB.x, wz); fma2(acc[1][3], hB.y, wz);
            fma2(acc[2][0], hA.x, wn); fma2(acc[2][1], hA.y, wn);
            fma2(acc[2][2], hB.x, wn); fma2(acc[2][3], hB.y, wn);
        }
#pragma unroll
        for (int g = 0; g < 3; g++)
#pragma unroll
            for (int p = 0; p < 4; p++) {
                ull o = __shfl_xor_sync(0xffffffffu, acc[g][p], 16);
                acc[g][p] = add2(acc[g][p], o);
            }
        if (lane < 16) {
#pragma unroll
            for (int g = 0; g < 3; g++)
#pragma unroll
                for (int p = 0; p < 4; p++)
                    *(ull*)&S->part[(((wid * 16 + j) * 3 + g) * 5 + p) * 2] = acc[g][p];
        }
        __syncthreads();
        if (tid < 128) {
#pragma unroll
            for (int w = 0; w < 8; w++) {
                const float* pp = &S->part[((w * 16 + j) * 3) * 10 + fb];
                xr += pp[0];
                xz += pp[10];
                xn += pp[20];
            }
        }
    }

    // ---- stage x(1) into xbuf[0]; load h0 into S->h ----
    {
        const float* xsrc = g_xt + ((size_t)(bg * 1024 + 1) * 512) * 8;
#pragma unroll
        for (int i = 0; i < 4; i++) {
            int q = (tid + 256 * i) << 2;
            float4 v = __ldg((const float4*)&xsrc[q]);
            *(float4*)&S->x[0][q] = v;
        }
        const float* hsrc = h0 + (size_t)bg * 8 * 512;
        for (int q = tid; q < 1024; q += 256) {
            int b8 = q >> 7, kq = (q & 127) << 2;
            float4 v = *(const float4*)&hsrc[b8 * 512 + kq];
            S->h[(kq + 0) * 8 + b8] = v.x;
            S->h[(kq + 1) * 8 + b8] = v.y;
            S->h[(kq + 2) * 8 + b8] = v.z;
            S->h[(kq + 3) * 8 + b8] = v.w;
        }
    }
    __syncthreads();

    for (int t = 0; t < Tlen; t++) {
        const bool more = (t < Tlen - 1);
        // issue LDG for x(t+2) early (hidden under scan compute)
        float4 x4[4];
        const bool havex = (t + 2 < Tlen);
        if (havex) {
            const float* xsrc = g_xt + ((size_t)(bg * 1024 + t + 2) * 512) * 8;
#pragma unroll
            for (int i = 0; i < 4; i++)
                x4[i] = __ldg((const float4*)&xsrc[(tid + 256 * i) << 2]);
        }

        // ---- scan dots: h(t) @ w_hh ----
        ull acc[3][4];
#pragma unroll
        for (int g = 0; g < 3; g++)
#pragma unroll
            for (int p = 0; p < 4; p++) acc[g][p] = 0ull;
#pragma unroll 4
        for (int kk = 0; kk < 32; kk++) {
            int k = k0 + kk;
            const float* hp = &S->h[k * 8];
            ulonglong2 hA = *(const ulonglong2*)(hp);
            ulonglong2 hB = *(const ulonglong2*)(hp + 4);
            const float* wp = &S->w[k * SK_W];
            ull wr = pack2(wp[j]);
            ull wz = pack2(wp[16 + j]);
            ull wn = pack2(wp[32 + j]);
            fma2(acc[0][0], hA.x, wr); fma2(acc[0][1], hA.y, wr);
            fma2(acc[0][2], hB.x, wr); fma2(acc[0][3], hB.y, wr);
            fma2(acc[1][0], hA.x, wz); fma2(acc[1][1], hA.y, wz);
            fma2(acc[1][2], hB.x, wz); fma2(acc[1][3], hB.y, wz);
            fma2(acc[2][0], hA.x, wn); fma2(acc[2][1], hA.y, wn);
            fma2(acc[2][2], hB.x, wn); fma2(acc[2][3], hB.y, wn);
        }
#pragma unroll
        for (int g = 0; g < 3; g++)
#pragma unroll
            for (int p = 0; p < 4; p++) {
                ull o = __shfl_xor_sync(0xffffffffu, acc[g][p], 16);
                acc[g][p] = add2(acc[g][p], o);
            }
        if (lane < 16) {
#pragma unroll
            for (int g = 0; g < 3; g++)
#pragma unroll
                for (int p = 0; p < 4; p++)
                    *(ull*)&S->part[(((wid * 16 + j) * 3 + g) * 5 + p) * 2] = acc[g][p];
        }
        __syncthreads();   // A

        // ---- gates + h store ----
        float hnew = 0.f;
        if (tid < 128) {
            float sr = 0.f, sz = 0.f, sn = 0.f;
#pragma unroll
            for (int w = 0; w < 8; w++) {
                const float* pp = &S->part[((w * 16 + j) * 3) * 10 + fb];
                sr += pp[0];
                sz += pp[10];
                sn += pp[20];
            }
            float r = 1.f / (1.f + __expf(-(sr + xr + b_r)));
            float z = 1.f / (1.f + __expf(-(sz + xz + b_z)));
            float n = tanhf(xn + b_n + r * (sn + b_hn));
            float hprev = S->h[jgl * 8 + fb];
            hnew = (1.f - z) * n + z * hprev;
            if (more) g_ht[(t + 1) & 1][bg][jgl * 8 + fb] = hnew;
        }
        __syncthreads();   // B: part consumed, h stores ordered

        if (more) {
            if (tid == 0) {
                unsigned* bp = &g_bar[bg * Tlen + t];
                asm volatile("red.release.gpu.global.add.u32 [%0], %1;"
                             :: "l"(bp), "r"(1u) : "memory");
            }

            // ---- shadow work: xg(t+1) GEMM phase (w_ih in regs) ----
            {
                ull acc2[3][4];
#pragma unroll
                for (int g = 0; g < 3; g++)
#pragma unroll
                    for (int p = 0; p < 4; p++) acc2[g][p] = 0ull;
                const float* xp = &S->x[t & 1][0];
#pragma unroll
                for (int kk = 0; kk < 32; kk++) {
                    int k = k0 + kk;
                    ulonglong2 hA = *(const ulonglong2*)&xp[k * 8];
                    ulonglong2 hB = *(const ulonglong2*)&xp[k * 8 + 4];
                    ull wr = pack2(wr_ih[kk]);
                    ull wz = pack2(wz_ih[kk]);
                    ull wn = pack2(wn_ih[kk]);
                    fma2(acc2[0][0], hA.x, wr); fma2(acc2[0][1], hA.y, wr);
                    fma2(acc2[0][2], hB.x, wr); fma2(acc2[0][3], hB.y, wr);
                    fma2(acc2[1][0], hA.x, wz); fma2(acc2[1][1], hA.y, wz);
                    fma2(acc2[1][2], hB.x, wz); fma2(acc2[1][3], hB.y, wz);
                    fma2(acc2[2][0], hA.x, wn); fma2(acc2[2][1], hA.y, wn);
                    fma2(acc2[2][2], hB.x, wn); fma2(acc2[2][3], hB.y, wn);
                }
#pragma unroll
                for (int g = 0; g < 3; g++)
#pragma unroll
                    for (int p = 0; p < 4; p++) {
                        ull o = __shfl_xor_sync(0xffffffffu, acc2[g][p], 16);
                        acc2[g][p] = add2(acc2[g][p], o);
                    }
                if (lane < 16) {
#pragma unroll
                    for (int g = 0; g < 3; g++)
#pragma unroll
                        for (int p = 0; p < 4; p++)
                            *(ull*)&S->part[(((wid * 16 + j) * 3 + g) * 5 + p) * 2] = acc2[g][p];
                }
            }
            __syncthreads();   // C
            if (tid < 128) {
                xr = 0.f; xz = 0.f; xn = 0.f;
#pragma unroll
                for (int w = 0; w < 8; w++) {
                    const float* pp = &S->part[((w * 16 + j) * 3) * 10 + fb];
                    xr += pp[0];
                    xz += pp[10];
                    xn += pp[20];
                }
                // out store in shadow
                out[((size_t)(bg * 8 + fb) * 1024 + t) * 512 + jgl] = hnew;
            }
            // stage x(t+2) into other buffer
            if (havex) {
#pragma unroll
                for (int i = 0; i < 4; i++)
                    *(float4*)&S->x[(t + 1) & 1][(tid + 256 * i) << 2] = x4[i];
            }

            if (tid == 0) {
                unsigned* bp = &g_bar[bg * Tlen + t];
                unsigned vv;
                do {
                    asm volatile("ld.acquire.gpu.global.u32 %0, [%1];"
                                 : "=r"(vv) : "l"(bp) : "memory");
                } while (vv < 32u);
            }
            __syncthreads();   // D

            // ---- pull h(t+1) ----
            const float* hsrc = &g_ht[(t + 1) & 1][bg][0];
#pragma unroll
            for (int i = 0; i < 4; i++) {
                int q = (tid + 256 * i) << 2;
                float4 v = __ldcg((const float4*)&hsrc[q]);
                *(float4*)&S->h[q] = v;
            }
            __syncthreads();   // E
        } else {
            if (tid < 128) {
                out[((size_t)(bg * 8 + fb) * 1024 + t) * 512 + jgl] = hnew;
                if (write_last)
                    out[(size_t)Bsz * Tlen * Hh + (bg * 8 + fb) * 512 + jgl] = hnew;
            }
        }
    }
}

// ---------------- launch ----------------
extern "C" void kernel_launch(void* const* d_in, const int* in_sizes, int n_in,
                              void* d_out, int out_size) {
    const float* x       = (const float*)d_in[0];
    const float* h0      = (const float*)d_in[1];
    const float* wih_mu  = (const float*)d_in[2];
    const float* wih_rho = (const float*)d_in[3];
    const float* whh_mu  = (const float*)d_in[4];
    const float* whh_rho = (const float*)d_in[5];
    const float* b_mu    = (const float*)d_in[6];
    const float* b_rho   = (const float*)d_in[7];
    const float* eps_ih  = (const float*)d_in[8];
    const float* eps_hh  = (const float*)d_in[9];
    const float* eps_b   = (const float*)d_in[10];
    float* out = (float*)d_out;

    {
        int total = Dd * NG + 32 * 512 * 48 + C4H + 4 * Tlen;
        int blocks = (total + 255) / 256;
        sample_all_kernel<<<blocks, 256>>>(wih_mu, wih_rho, eps_ih,
                                           whh_mu, whh_rho, eps_hh,
                                           b_mu, b_rho, eps_b);
    }
    {
        int threads = 4 * 1024 * 128 * 8;   // 4194304
        xpose_kernel<<<threads / 256, 256>>>(x);
    }
    {
        int smem = (int)sizeof(ScanSmem);
        cudaFuncSetAttribute(scan_kernel, cudaFuncAttributeMaxDynamicSharedMemorySize, smem);
        int write_last = (out_size >= Bsz * Tlen * Hh + Bsz * Hh) ? 1 : 0;
        scan_kernel<<<128, 256, smem>>>(h0, out, write_last);
    }
}